// round 6
// baseline (speedup 1.0000x reference)
#include <cuda_runtime.h>

typedef unsigned long long ull;

// ---------------------------------------------------------------------------
// Multi-scale residual VQ: B=64, C=32, H=W=16, vocab=4096,
// scales pn = 1,2,3,4,5,6,8,10,13,16 (last = identity, no resize).
// Per scale: area-downsample -> fp32 FFMA2 distance GEMM + fused argmin ->
// gather + bicubic upsample -> residual update. All graph-capturable.
// ---------------------------------------------------------------------------

__constant__ int d_PN[10] = {1,2,3,4,5,6,8,10,13,16};

__device__ __align__(16) float g_frest[64*16*16*32];   // BHWC residual
__device__ __align__(16) float g_fhat [64*16*16*32];   // BHWC accumulator
__device__ __align__(16) float g_z    [10816*32];      // downsampled tokens (max pn=13)
__device__ __align__(16) float g_embP [16*4096*2];     // e pairs, layout [kp][code][2]
__device__ float g_esq  [4096];                        // ||e||^2 per code
__device__ float g_ps   [65536];                       // partial argmin scores
__device__ int   g_pi   [65536];                       // partial argmin indices
__device__ float g_upw  [9][16][13];                   // bicubic weights per non-last scale

#define FFMA2(d,a,b) asm("fma.rn.f32x2 %0, %1, %2, %0;" : "+l"(d) : "l"(a), "l"(b))

// ---------------- init ----------------

__global__ void k_init(const float* __restrict__ f){
    int i = blockIdx.x*256 + threadIdx.x;              // BHWC linear
    int c = i & 31, x = (i>>5)&15, y = (i>>9)&15, b = i>>13;
    g_frest[i] = f[((b*32+c)*16+y)*16+x];
    g_fhat[i]  = 0.f;
}

__global__ void k_init_emb(const float* __restrict__ emb){
    int j = blockIdx.x*256 + threadIdx.x;              // code id
    float s = 0.f;
#pragma unroll
    for (int kp = 0; kp < 16; kp++){
        float a = emb[j*32 + 2*kp];
        float b = emb[j*32 + 2*kp + 1];
        s = __fmaf_rn(a, a, s);
        s = __fmaf_rn(b, b, s);
        g_embP[(kp*4096 + j)*2 + 0] = a;
        g_embP[(kp*4096 + j)*2 + 1] = b;
    }
    g_esq[j] = s;
}

__device__ __forceinline__ float keys_cubic(float x){
    if (x >= 2.f) return 0.f;
    if (x >= 1.f) return ((-0.5f*x + 2.5f)*x - 4.f)*x + 2.f;
    return ((1.5f*x - 2.5f)*x)*x + 1.f;
}

// jax.image.resize cubic weights: half-pixel sampling, Keys a=-0.5,
// normalize by the (truncated) weight sum.
__global__ void k_init_w(){
    int t = threadIdx.x;
    if (t >= 144) return;                 // 9 non-last scales x 16 outputs
    int si = t >> 4, i = t & 15;
    int pn = d_PN[si];
    float sf = (i + 0.5f) * ((float)pn / 16.f) - 0.5f;
    float w[13]; float tot = 0.f;
    for (int j = 0; j < pn; j++){
        float v = keys_cubic(fabsf(sf - (float)j));
        w[j] = v; tot += v;
    }
    bool ok = fabsf(tot) > 1.1920929e-4f; // 1000 * eps(f32)
    for (int j = 0; j < pn; j++)
        g_upw[si][i][j] = ok ? (w[j] / tot) : 0.f;
}

// ---------------- area downsample (adaptive_avg_pool windows) ----------------

__global__ void k_down(int pn, int total){
    int i = blockIdx.x*256 + threadIdx.x;
    if (i >= total) return;
    int c = i & 31; int n = i >> 5;                    // n = (b*pn+p)*pn+q
    int pp = n / pn; int q = n - pp*pn;
    int b  = pp / pn; int p = pp - b*pn;
    int sh = (p*16)/pn, eh = ((p+1)*16 + pn - 1)/pn;
    int sw = (q*16)/pn, ew = ((q+1)*16 + pn - 1)/pn;
    float s = 0.f;
    for (int y = sh; y < eh; y++)
        for (int x = sw; x < ew; x++)
            s += g_frest[((b*16+y)*16 + x)*32 + c];
    g_z[i] = s * (1.f/(float)((eh-sh)*(ew-sw)));
}

// ---------------- fused distance GEMM + argmin (FFMA2) ----------------
// grid = (tokens/64, nseg). CTA: 64 tokens x segCodes codes (tiles of 128).
// warp w owns tokens w*8..w*8+7; lane owns 4 codes per tile.
// d = fl(fl(zsq + esq) - 2*p)  — replicates the reference rounding.

__global__ __launch_bounds__(256,2)
void k_argmin(int segCodes, int nseg, int useRest){
    __shared__ ull  z2[16][64];     // [kpair][token] packed (f32,f32)
    __shared__ float zsq[64];
    int t = threadIdx.x;
    int tokBase = blockIdx.x * 64;
    int codeBase = blockIdx.y * segCodes;

    const ull* gz2 = useRest ? (const ull*)g_frest : (const ull*)g_z;
    for (int i = t; i < 1024; i += 256){
        int tok = i >> 4, kp = i & 15;
        z2[kp][tok] = gz2[(size_t)(tokBase + tok)*16 + kp];
    }
    __syncthreads();
    if (t < 64){
        float s = 0.f;
        for (int kp = 0; kp < 16; kp++){
            ull v = z2[kp][t];
            float lo = __uint_as_float((unsigned)(v & 0xffffffffULL));
            float hi = __uint_as_float((unsigned)(v >> 32));
            s = __fmaf_rn(lo, lo, s);
            s = __fmaf_rn(hi, hi, s);
        }
        zsq[t] = s;
    }
    __syncthreads();

    int w = t >> 5, lane = t & 31;
    int row0 = w * 8;
    float best[8]; int bidx[8];
#pragma unroll
    for (int r = 0; r < 8; r++){ best[r] = 3.4e38f; bidx[r] = 0; }

    const ull* ep = (const ull*)g_embP;      // [kp*4096 + code]

    for (int c0 = codeBase; c0 < codeBase + segCodes; c0 += 128){
        int myc = c0 + lane*4;
        ull acc[8][4];
#pragma unroll
        for (int r = 0; r < 8; r++)
#pragma unroll
            for (int j = 0; j < 4; j++) acc[r][j] = 0ULL;

#pragma unroll
        for (int kp = 0; kp < 16; kp++){
            ull zv[8];
#pragma unroll
            for (int r = 0; r < 8; r++) zv[r] = z2[kp][row0 + r];
#pragma unroll
            for (int j = 0; j < 4; j++){
                ull ev = __ldg(&ep[kp*4096 + myc + j]);
#pragma unroll
                for (int r = 0; r < 8; r++) FFMA2(acc[r][j], zv[r], ev);
            }
        }
        // epilogue: distances + per-thread argmin (codes ascending -> first-min)
#pragma unroll
        for (int j = 0; j < 4; j++){
            float esq_j = __ldg(&g_esq[myc + j]);
#pragma unroll
            for (int r = 0; r < 8; r++){
                ull a = acc[r][j];
                float lo = __uint_as_float((unsigned)(a & 0xffffffffULL));
                float hi = __uint_as_float((unsigned)(a >> 32));
                float p  = __fadd_rn(lo, hi);
                float s1 = __fadd_rn(zsq[row0 + r], esq_j);
                float d  = __fmaf_rn(-2.f, p, s1);
                if (d < best[r]){ best[r] = d; bidx[r] = myc + j; }
            }
        }
    }
    // cross-lane reduce per row; tie -> lower code index (matches argmin)
#pragma unroll
    for (int r = 0; r < 8; r++){
        float v = best[r]; int i = bidx[r];
        for (int off = 16; off; off >>= 1){
            float vo = __shfl_xor_sync(0xffffffffu, v, off);
            int   io = __shfl_xor_sync(0xffffffffu, i, off);
            if (vo < v || (vo == v && io < i)){ v = vo; i = io; }
        }
        if (lane == 0){
            int tok = tokBase + row0 + r;
            g_ps[tok*nseg + blockIdx.y] = v;
            g_pi[tok*nseg + blockIdx.y] = i;
        }
    }
}

// ---------------- gather + bicubic upsample + residual update ----------------
// grid = 64 (batch). Inline segment reduction, separable upsample in smem.

__global__ void k_apply(int pn, int si, int nseg, const float* __restrict__ emb){
    __shared__ float t1[13*16*32];   // [p][x][c]
    __shared__ float Wm[16][13];
    __shared__ int   idx_s[169];
    int b = blockIdx.x, t = threadIdx.x;
    int pp = pn*pn;

    if (t < pp){
        int tok = b*pp + t;
        float bv = g_ps[tok*nseg]; int bi = g_pi[tok*nseg];
        for (int s = 1; s < nseg; s++){
            float v = g_ps[tok*nseg + s]; int i = g_pi[tok*nseg + s];
            if (v < bv || (v == bv && i < bi)){ bv = v; bi = i; }
        }
        idx_s[t] = bi;
    }
    if (t < 16*pn) Wm[t/pn][t%pn] = g_upw[si][t/pn][t%pn];
    __syncthreads();

    int n1 = pn*512;                         // pn * 16 * 32
    for (int e = t; e < n1; e += 256){
        int c = e & 31, x = (e>>5)&15, p = e >> 9;
        float s = 0.f;
        for (int q = 0; q < pn; q++)
            s = __fmaf_rn(Wm[x][q], emb[idx_s[p*pn+q]*32 + c], s);
        t1[e] = s;
    }
    __syncthreads();

    for (int e = t; e < 8192; e += 256){
        int c = e & 31, x = (e>>5)&15, y = e >> 9;
        float o = 0.f;
        for (int p = 0; p < pn; p++)
            o = __fmaf_rn(Wm[y][p], t1[(p*16+x)*32 + c], o);
        int g = ((b*16+y)*16 + x)*32 + c;
        g_fhat[g]  = g_fhat[g]  + o;
        g_frest[g] = g_frest[g] - o;
    }
}

// ---------------- last scale: gather (no resize) + add + BCHW transpose ----

__global__ void k_last(int nseg, const float* __restrict__ emb, float* __restrict__ out){
    int i = blockIdx.x*256 + threadIdx.x;    // BCHW linear
    int x = i & 15, y = (i>>4)&15, c = (i>>8)&31, b = i>>13;
    int tok = (b*16+y)*16 + x;
    float bv = g_ps[tok*nseg]; int bi = g_pi[tok*nseg];
    for (int s = 1; s < nseg; s++){
        float v = g_ps[tok*nseg + s]; int ii = g_pi[tok*nseg + s];
        if (v < bv || (v == bv && ii < bi)){ bv = v; bi = ii; }
    }
    out[i] = g_fhat[tok*32 + c] + emb[bi*32 + c];
}

// ---------------- host ----------------

extern "C" void kernel_launch(void* const* d_in, const int* in_sizes, int n_in,
                              void* d_out, int out_size){
    const float* f   = (const float*)d_in[0];
    const float* emb = (const float*)d_in[1];
    if (n_in >= 2 && in_sizes[0] == 4096*32 && in_sizes[1] == 64*32*16*16){
        const float* tmp = f; f = emb; emb = tmp;   // defensive order check
    }

    static const int PNs [10] = {1, 2, 3, 4, 5, 6, 8, 10, 13, 16};
    static const int SEGs[10] = {32,16, 8, 8, 4, 4, 4,  2,  2,  2};

    k_init    <<<2048, 256>>>(f);
    k_init_emb<<<16,   256>>>(emb);
    k_init_w  <<<1,    160>>>();

    for (int si = 0; si < 10; si++){
        int pn = PNs[si], pp = pn*pn, ntok = 64*pp;
        bool last = (si == 9);
        if (!last){
            int total = ntok*32;
            k_down<<<(total + 255)/256, 256>>>(pn, total);
        }
        int seg = SEGs[si], segc = 4096/seg;
        dim3 g(ntok/64, seg);
        k_argmin<<<g, 256>>>(segc, seg, last ? 1 : 0);
        if (!last) k_apply<<<64, 256>>>(pn, si, seg, emb);
        else       k_last <<<2048, 256>>>(seg, emb, (float*)d_out);
    }
}

// round 15
// speedup vs baseline: 1.2563x; 1.2563x over previous
#include <cuda_runtime.h>

typedef unsigned long long ull;

// ---------------------------------------------------------------------------
// Multi-scale residual VQ: B=64, C=32, H=W=16, vocab=4096,
// scales pn = 1,2,3,4,5,6,8,10,13,16 (last = identity).
// cp.async-staged FFMA2 argmin (64-code tiles, 3-stage ring), 64-bit key
// argmin, downsample fused into init/apply (no k_down launches).
// R10 fix: do NOT compute the fused downsample for the last scale (pn=16
// reads g_frest directly) — R6 wrote 524288 floats into the 346112-float
// g_z, trampling adjacent globals (-> rel_err 0.29).
// R12: identical resubmit of R10/R11 source (R11 bench was an infra failure;
// the kernel never ran).
// ---------------------------------------------------------------------------

__constant__ int d_PN[10] = {1,2,3,4,5,6,8,10,13,16};

__device__ __align__(16) float g_frest[64*16*16*32];   // BHWC residual
__device__ __align__(16) float g_fhat [64*16*16*32];   // BHWC accumulator
__device__ __align__(16) float g_z    [10816*32];      // downsampled tokens (max pn=13)
__device__ __align__(16) float g_embP [16*4096*2];     // e pairs, [kp][code][2]
__device__ float g_esq  [4096];                        // ||e||^2 per code
__device__ ull   g_pk   [131072];                      // partial argmin keys
__device__ float g_upw  [9][16][13];                   // bicubic weights per non-last scale

#define FFMA2(d,a,b) asm("fma.rn.f32x2 %0, %1, %2, %0;" : "+l"(d) : "l"(a), "l"(b))

__device__ __forceinline__ void cpa16(unsigned s, const void* g){
    asm volatile("cp.async.cg.shared.global [%0], [%1], 16;" :: "r"(s), "l"(g));
}
#define CPA_COMMIT()  asm volatile("cp.async.commit_group;")
#define CPA_WAIT1()   asm volatile("cp.async.wait_group 1;")

// ---------------- init: emb prep (+ bicubic weights in block 0) -------------

__device__ __forceinline__ float keys_cubic(float x){
    if (x >= 2.f) return 0.f;
    if (x >= 1.f) return ((-0.5f*x + 2.5f)*x - 4.f)*x + 2.f;
    return ((1.5f*x - 2.5f)*x)*x + 1.f;
}

__global__ void k_init_emb(const float* __restrict__ emb){
    int j = blockIdx.x*256 + threadIdx.x;              // code id
    float s = 0.f;
#pragma unroll
    for (int kp = 0; kp < 16; kp++){
        float a = emb[j*32 + 2*kp];
        float b = emb[j*32 + 2*kp + 1];
        s = __fmaf_rn(a, a, s);
        s = __fmaf_rn(b, b, s);
        g_embP[(kp*4096 + j)*2 + 0] = a;
        g_embP[(kp*4096 + j)*2 + 1] = b;
    }
    g_esq[j] = s;

    if (blockIdx.x == 0 && threadIdx.x < 144){         // 9 scales x 16 outputs
        int t = threadIdx.x;
        int si = t >> 4, i = t & 15;
        int pn = d_PN[si];
        float sf = (i + 0.5f) * ((float)pn / 16.f) - 0.5f;
        float w[13]; float tot = 0.f;
        for (int j2 = 0; j2 < pn; j2++){
            float v = keys_cubic(fabsf(sf - (float)j2));
            w[j2] = v; tot += v;
        }
        bool ok = fabsf(tot) > 1.1920929e-4f;          // 1000 * eps(f32)
        for (int j2 = 0; j2 < pn; j2++)
            g_upw[si][i][j2] = ok ? (w[j2] / tot) : 0.f;
    }
}

// ---------------- init: BCHW->BHWC transpose + fused downsample pn=1 --------

__global__ void k_init(const float* __restrict__ f){
    __shared__ float sm[256*33];                       // [pixel][c], pad 33
    int b = blockIdx.x, t = threadIdx.x;
    for (int l = t; l < 8192; l += 256){               // l = c*256 + y*16 + x
        int c = l >> 8, yx = l & 255;
        sm[yx*33 + c] = f[b*8192 + l];
    }
    __syncthreads();
    for (int l = t; l < 8192; l += 256){               // l = pix*32 + c (BHWC)
        int c = l & 31, pix = l >> 5;
        g_frest[b*8192 + l] = sm[pix*33 + c];
        g_fhat [b*8192 + l] = 0.f;
    }
    if (t < 32){                                       // pn=1 downsample
        float s = 0.f;
        for (int y = 0; y < 16; y++)
            for (int x = 0; x < 16; x++)
                s += sm[(y*16+x)*33 + t];
        g_z[b*32 + t] = s * (1.f/256.f);
    }
}

// ---------------- fused distance GEMM + argmin --------------------------
// grid=(ntok/64, nseg). CTA: 64 tokens x (segTiles*64) codes.
// Thread: 8 tokens x 2 codes. emb tiles staged via cp.async (3-stage ring).
// d = fl(fl(zsq+esq) - 2*fl(p_lo+p_hi))  — identical rounding to reference.

__global__ __launch_bounds__(256,2)
void k_argmin(int segTiles, int nseg, int useRest){
    __shared__ ull  z2t[64][16];        // [token][kp]
    __shared__ float zsq[64];
    __shared__ ull  es[3][16][64];      // staged emb tiles

    int t = threadIdx.x;
    int tokBase = blockIdx.x * 64;
    int tileBase = blockIdx.y * segTiles;
    const ull* gz = useRest ? (const ull*)g_frest : (const ull*)g_z;
    const ull* ep = (const ull*)g_embP;

    for (int i = t; i < 1024; i += 256)
        z2t[i>>4][i&15] = gz[(size_t)tokBase*16 + i];

    // prefetch tiles 0,1 (512 x 16B chunks per tile; 2 chunks/thread)
#pragma unroll
    for (int st = 0; st < 2; st++){
        int c0 = (tileBase + st)*64;
#pragma unroll
        for (int h = 0; h < 2; h++){
            int ch = t + h*256;
            int kp = ch >> 5, pos = (ch & 31)*2;
            cpa16((unsigned)__cvta_generic_to_shared(&es[st][kp][pos]),
                  &ep[kp*4096 + c0 + pos]);
        }
        CPA_COMMIT();
    }
    __syncthreads();
    if (t < 64){
        float s = 0.f;
#pragma unroll
        for (int kp = 0; kp < 16; kp++){
            ull v = z2t[t][kp];
            float lo = __uint_as_float((unsigned)(v & 0xffffffffULL));
            float hi = __uint_as_float((unsigned)(v >> 32));
            s = __fmaf_rn(lo, lo, s);
            s = __fmaf_rn(hi, hi, s);
        }
        zsq[t] = s;
    }

    int w = t >> 5, lane = t & 31;
    int row0 = w * 8;
    ull bestKey[8];
#pragma unroll
    for (int r = 0; r < 8; r++) bestKey[r] = ~0ULL;

    for (int tt = 0; tt < segTiles; tt++){
        CPA_WAIT1();
        __syncthreads();                 // tile tt visible; all done with tile tt-1
        if (tt + 2 < segTiles){
            int st = (tt + 2) % 3;
            int c0 = (tileBase + tt + 2)*64;
#pragma unroll
            for (int h = 0; h < 2; h++){
                int ch = t + h*256;
                int kp = ch >> 5, pos = (ch & 31)*2;
                cpa16((unsigned)__cvta_generic_to_shared(&es[st][kp][pos]),
                      &ep[kp*4096 + c0 + pos]);
            }
        }
        CPA_COMMIT();

        const ull (*eb)[64] = es[tt % 3];
        ull acc[8][2];
#pragma unroll
        for (int r = 0; r < 8; r++){ acc[r][0] = 0ULL; acc[r][1] = 0ULL; }

#pragma unroll
        for (int kp = 0; kp < 16; kp++){
            ull e0 = eb[kp][lane];
            ull e1 = eb[kp][lane+32];
#pragma unroll
            for (int r = 0; r < 8; r++){
                ull zv = z2t[row0 + r][kp];
                FFMA2(acc[r][0], zv, e0);
                FFMA2(acc[r][1], zv, e1);
            }
        }
        int cbase = (tileBase + tt)*64;
#pragma unroll
        for (int j = 0; j < 2; j++){
            int code = cbase + lane + j*32;
            float esq_j = __ldg(&g_esq[code]);
#pragma unroll
            for (int r = 0; r < 8; r++){
                ull a  = acc[r][j];
                float lo = __uint_as_float((unsigned)(a & 0xffffffffULL));
                float hi = __uint_as_float((unsigned)(a >> 32));
                float p  = __fadd_rn(lo, hi);
                float s1 = __fadd_rn(zsq[row0 + r], esq_j);
                float d  = __fmaf_rn(-2.f, p, s1);     // d > 0 here
                ull key = ((ull)__float_as_uint(d) << 32) | (unsigned)code;
                if (key < bestKey[r]) bestKey[r] = key;
            }
        }
    }
#pragma unroll
    for (int r = 0; r < 8; r++){
        ull k = bestKey[r];
        for (int off = 16; off; off >>= 1){
            ull ko = __shfl_xor_sync(0xffffffffu, k, off);
            if (ko < k) k = ko;
        }
        if (lane == 0)
            g_pk[(size_t)(tokBase + row0 + r)*nseg + blockIdx.y] = k;
    }
}

// ------- gather + bicubic upsample + residual update + fused downsample -----
// grid = 64 (batch). pnN = next scale's pn, or 0 when the next scale is the
// last (it reads g_frest directly; writing g_z for pn=16 would overflow it).

__global__ void k_apply(int pn, int si, int nseg, int pnN,
                        const float* __restrict__ emb){
    __shared__ float t1[13*16*32];   // [p][x][c]
    __shared__ float Wm[16][13];
    __shared__ int   idx_s[169];
    int b = blockIdx.x, t = threadIdx.x;
    int pp = pn*pn;

    if (t < pp){
        size_t tok = (size_t)(b*pp + t);
        ull k = g_pk[tok*nseg];
        for (int s = 1; s < nseg; s++){
            ull v = g_pk[tok*nseg + s];
            if (v < k) k = v;
        }
        idx_s[t] = (int)(unsigned)(k & 0xffffffffULL);
    }
    if (t < 16*pn) Wm[t/pn][t%pn] = g_upw[si][t/pn][t%pn];
    __syncthreads();

    int n1 = pn*512;                         // pn * 16 * 32
    for (int e = t; e < n1; e += 256){
        int c = e & 31, x = (e>>5)&15, p = e >> 9;
        float s = 0.f;
        for (int q = 0; q < pn; q++)
            s = __fmaf_rn(Wm[x][q], emb[idx_s[p*pn+q]*32 + c], s);
        t1[e] = s;
    }
    __syncthreads();

    for (int e = t; e < 8192; e += 256){
        int c = e & 31, x = (e>>5)&15, y = e >> 9;
        float o = 0.f;
        for (int p = 0; p < pn; p++)
            o = __fmaf_rn(Wm[y][p], t1[(p*16+x)*32 + c], o);
        int g = b*8192 + ((y*16+x)*32 + c);
        g_fhat[g]  = g_fhat[g]  + o;
        g_frest[g] = g_frest[g] - o;
    }
    __syncthreads();                          // frest[b] updated & visible

    // fused downsample for next scale (skipped when pnN==0)
    int totN = pnN*pnN*32;
    for (int i = t; i < totN; i += 256){
        int c = i & 31; int n = i >> 5;       // n = p*pnN + q
        int p = n / pnN, q = n - p*pnN;
        int sh = (p*16)/pnN, eh = ((p+1)*16 + pnN - 1)/pnN;
        int sw = (q*16)/pnN, ew = ((q+1)*16 + pnN - 1)/pnN;
        float s = 0.f;
        for (int y = sh; y < eh; y++)
            for (int x = sw; x < ew; x++)
                s += g_frest[b*8192 + ((y*16+x)*32 + c)];
        g_z[(size_t)b*totN + i] = s * (1.f/(float)((eh-sh)*(ew-sw)));
    }
}

// ---------------- last scale: gather + add + BCHW transpose ----------------

__global__ void k_last(int nseg, const float* __restrict__ emb,
                       float* __restrict__ out){
    int i = blockIdx.x*256 + threadIdx.x;    // BCHW linear
    int x = i & 15, y = (i>>4)&15, c = (i>>8)&31, b = i>>13;
    size_t tok = (size_t)((b*16+y)*16 + x);
    ull k = g_pk[tok*nseg];
    for (int s = 1; s < nseg; s++){
        ull v = g_pk[tok*nseg + s];
        if (v < k) k = v;
    }
    int bi = (int)(unsigned)(k & 0xffffffffULL);
    out[i] = g_fhat[tok*32 + c] + emb[bi*32 + c];
}

// ---------------- host ----------------

extern "C" void kernel_launch(void* const* d_in, const int* in_sizes, int n_in,
                              void* d_out, int out_size){
    const float* f   = (const float*)d_in[0];
    const float* emb = (const float*)d_in[1];
    if (n_in >= 2 && in_sizes[0] == 4096*32 && in_sizes[1] == 64*32*16*16){
        const float* tmp = f; f = emb; emb = tmp;   // defensive order check
    }

    static const int PNs [10] = {1, 2, 3, 4, 5, 6, 8, 10, 13, 16};
    static const int SEGs[10] = {32,32,32,32,32,16, 8,  8,  8,  8};

    k_init_emb<<<16, 256>>>(emb);
    k_init    <<<64, 256>>>(f);

    for (int si = 0; si < 10; si++){
        int pn = PNs[si], pp = pn*pn, ntok = 64*pp;
        bool last = (si == 9);
        int seg = SEGs[si], segTiles = 64/seg;    // tiles of 64 codes
        dim3 g(ntok/64, seg);
        k_argmin<<<g, 256>>>(segTiles, seg, last ? 1 : 0);
        if (!last){
            int pnN = (si < 8) ? PNs[si+1] : 0;   // si=8 -> next is last: skip
            k_apply<<<64, 256>>>(pn, si, seg, pnN, emb);
        } else {
            k_last <<<2048, 256>>>(seg, emb, (float*)d_out);
        }
    }
}